// round 7
// baseline (speedup 1.0000x reference)
#include <cuda_runtime.h>
#include <math.h>

#define N_NODES_MAX 50000
#define N_EDGES_MAX 400000

// ---------------- scratch (device globals; no allocation) ----------------
// agg rows: l0: [0, N)           (n)        d=1
//           l1: [N, 4N)          (n*3+i)    d=3
//           l2: [4N, 9N)         (n*5+i)    d=5
//           l3: [9N, 16N)        (n*7+i)    d=7
// each row has 32 floats (m-contiguous)
__device__ float g_agg[(size_t)16 * N_NODES_MAX * 32];
__device__ int   g_deg[N_NODES_MAX];
__device__ int   g_rowstart[N_NODES_MAX + 1];
__device__ int   g_cursor[N_NODES_MAX];
__device__ int   g_perm[N_EDGES_MAX];
__device__ int   g_bsum[64];
__device__ int   g_boff[64];

// ---------------- CSR build ----------------
__global__ void k_zero(int n) {
    int i = blockIdx.x * blockDim.x + threadIdx.x;
    if (i < n) { g_deg[i] = 0; g_cursor[i] = 0; }
}

__global__ void k_hist(const int* __restrict__ recv, int e) {
    int i = blockIdx.x * blockDim.x + threadIdx.x;
    if (i < e) atomicAdd(&g_deg[recv[i]], 1);
}

__global__ void k_scan1(int n) {
    __shared__ int sm[1024];
    int i = blockIdx.x * 1024 + threadIdx.x;
    int v = (i < n) ? g_deg[i] : 0;
    sm[threadIdx.x] = v;
    __syncthreads();
    for (int off = 1; off < 1024; off <<= 1) {
        int t = (threadIdx.x >= off) ? sm[threadIdx.x - off] : 0;
        __syncthreads();
        sm[threadIdx.x] += t;
        __syncthreads();
    }
    if (i < n) g_rowstart[i + 1] = sm[threadIdx.x];
    if (threadIdx.x == 1023) g_bsum[blockIdx.x] = sm[1023];
}

__global__ void k_scan2(int nb) {
    if (threadIdx.x == 0 && blockIdx.x == 0) {
        int s = 0;
        for (int b = 0; b < nb; b++) { g_boff[b] = s; s += g_bsum[b]; }
        g_rowstart[0] = 0;
    }
}

__global__ void k_scan3(int n) {
    int i = blockIdx.x * 1024 + threadIdx.x;
    if (i < n) g_rowstart[i + 1] += g_boff[blockIdx.x];
}

__global__ void k_scatter(const int* __restrict__ recv, int e) {
    int i = blockIdx.x * blockDim.x + threadIdx.x;
    if (i < e) {
        int r = recv[i];
        int p = atomicAdd(&g_cursor[r], 1);
        g_perm[g_rowstart[r] + p] = i;
    }
}

// ---------------- edge gather + SH outer-product, warp per node ----------------
__global__ void __launch_bounds__(256) k_edge(
    const float* __restrict__ pos,
    const float* __restrict__ nf,
    const int* __restrict__ send,
    int n)
{
    const float S3  = 1.7320508075688772f;
    const float S5  = 2.2360679774997896f;
    const float S7  = 2.6457513110645906f;
    const float S15 = 3.872983346207417f;
    const float S42 = 6.480740698407860f;
    const float S70 = 8.366600265340756f;
    const float S105 = 10.246950765959598f;

    int warp = (blockIdx.x * blockDim.x + threadIdx.x) >> 5;
    int lane = threadIdx.x & 31;
    if (warp >= n) return;
    int nd = warp;

    float prx = pos[3 * nd + 0];
    float pry = pos[3 * nd + 1];
    float prz = pos[3 * nd + 2];

    float acc[16];
#pragma unroll
    for (int i = 0; i < 16; i++) acc[i] = 0.0f;

    int k0 = g_rowstart[nd];
    int k1 = g_rowstart[nd + 1];
    for (int k = k0; k < k1; k++) {
        int e  = g_perm[k];
        int sn = send[e];
        float sf = nf[(size_t)sn * 32 + lane];
        float dx = prx - pos[3 * sn + 0];
        float dy = pry - pos[3 * sn + 1];
        float dz = prz - pos[3 * sn + 2];
        float rr = sqrtf(dx * dx + dy * dy + dz * dz);
        float inv = 1.0f / fmaxf(rr, 1e-12f);
        float x = dx * inv, y = dy * inv, z = dz * inv;
        float x2 = x * x, y2 = y * y, z2 = z * z;

        acc[0] += sf;
        // l = 1
        acc[1] += sf * (S3 * x);
        acc[2] += sf * (S3 * y);
        acc[3] += sf * (S3 * z);
        // l = 2
        acc[4] += sf * (S15 * x * y);
        acc[5] += sf * (S15 * y * z);
        acc[6] += sf * (0.5f * S5 * (3.0f * z2 - 1.0f));
        acc[7] += sf * (S15 * x * z);
        acc[8] += sf * (0.5f * S15 * (x2 - y2));
        // l = 3
        acc[9]  += sf * (0.25f * S70 * y * (3.0f * x2 - y2));
        acc[10] += sf * (S105 * x * y * z);
        acc[11] += sf * (0.25f * S42 * y * (5.0f * z2 - 1.0f));
        acc[12] += sf * (0.5f * S7 * z * (5.0f * z2 - 3.0f));
        acc[13] += sf * (0.25f * S42 * x * (5.0f * z2 - 1.0f));
        acc[14] += sf * (0.5f * S105 * z * (x2 - y2));
        acc[15] += sf * (0.25f * S70 * x * (x2 - 3.0f * y2));
    }

    // store rows, i-major layout (coalesced: lane = m)
    g_agg[(size_t)(nd) * 32 + lane] = acc[0];
#pragma unroll
    for (int j = 0; j < 3; j++)
        g_agg[(size_t)(n + nd * 3 + j) * 32 + lane] = acc[1 + j];
#pragma unroll
    for (int j = 0; j < 5; j++)
        g_agg[(size_t)(4 * n + nd * 5 + j) * 32 + lane] = acc[4 + j];
#pragma unroll
    for (int j = 0; j < 7; j++)
        g_agg[(size_t)(9 * n + nd * 7 + j) * 32 + lane] = acc[9 + j];
}

// ---------------- node GEMM: (M x 32) @ (32 x 64) ----------------
// block = 128 threads, tile 64 rows x 64 cols; each thread 4x8 outputs.
// output element (row = n*D+i, col = t) -> out[n*1024 + outBase + t*D + i]
template <int D, bool SKIP>
__global__ void __launch_bounds__(128) k_gemm(
    const float* __restrict__ W,
    const float* __restrict__ A2,   // node_feats (SKIP only)
    const float* __restrict__ W2,   // Wsc (SKIP only)
    float* __restrict__ out,
    int rowBase, int M, int outBase,
    float s_agg, float s_skip)
{
    __shared__ float As[32][64];        // [k][row]
    __shared__ float Ws[2][32][64];     // [k][col]

    int tid  = threadIdx.x;
    int row0 = blockIdx.x * 64;
    int cx = tid & 7;    // cols cx*8 .. cx*8+7
    int ry = tid >> 3;   // rows ry*4 .. ry*4+3

    // load weights (row-major [m][t] == [k][col])
    for (int idx = tid; idx < 512; idx += 128) {
        ((float4*)&Ws[0][0][0])[idx] = ((const float4*)W)[idx];
        if (SKIP) ((float4*)&Ws[1][0][0])[idx] = ((const float4*)W2)[idx];
    }

    // load A tile transposed: As[k][r] = agg[(rowBase+row0+r)*32 + k]
    const float* Ag = g_agg + (size_t)rowBase * 32;
    for (int idx = tid; idx < 512; idx += 128) {
        int r = idx >> 3;
        int k4 = (idx & 7) * 4;
        float4 v = make_float4(0.f, 0.f, 0.f, 0.f);
        int row = row0 + r;
        if (row < M) v = *(const float4*)(Ag + (size_t)row * 32 + k4);
        As[k4 + 0][r] = v.x; As[k4 + 1][r] = v.y;
        As[k4 + 2][r] = v.z; As[k4 + 3][r] = v.w;
    }
    __syncthreads();

    float acc[4][8];
#pragma unroll
    for (int i = 0; i < 4; i++)
#pragma unroll
        for (int j = 0; j < 8; j++) acc[i][j] = 0.0f;

#pragma unroll
    for (int k = 0; k < 32; k++) {
        float4 a  = *(const float4*)&As[k][ry * 4];
        float4 w0 = *(const float4*)&Ws[0][k][cx * 8];
        float4 w1 = *(const float4*)&Ws[0][k][cx * 8 + 4];
        float av[4] = {a.x, a.y, a.z, a.w};
        float wv[8] = {w0.x, w0.y, w0.z, w0.w, w1.x, w1.y, w1.z, w1.w};
#pragma unroll
        for (int i = 0; i < 4; i++)
#pragma unroll
            for (int j = 0; j < 8; j++) acc[i][j] += av[i] * wv[j];
    }

    float finalScale;
    if (SKIP) {
        // out0 = (agg/8)@W0*s + nf@Wsc*s  -> acc *= 1/8, add skip pass, then *s
#pragma unroll
        for (int i = 0; i < 4; i++)
#pragma unroll
            for (int j = 0; j < 8; j++) acc[i][j] *= 0.125f;

        __syncthreads();
        for (int idx = tid; idx < 512; idx += 128) {
            int r = idx >> 3;
            int k4 = (idx & 7) * 4;
            float4 v = make_float4(0.f, 0.f, 0.f, 0.f);
            int row = row0 + r;
            if (row < M) v = *(const float4*)(A2 + (size_t)row * 32 + k4);
            As[k4 + 0][r] = v.x; As[k4 + 1][r] = v.y;
            As[k4 + 2][r] = v.z; As[k4 + 3][r] = v.w;
        }
        __syncthreads();

#pragma unroll
        for (int k = 0; k < 32; k++) {
            float4 a  = *(const float4*)&As[k][ry * 4];
            float4 w0 = *(const float4*)&Ws[1][k][cx * 8];
            float4 w1 = *(const float4*)&Ws[1][k][cx * 8 + 4];
            float av[4] = {a.x, a.y, a.z, a.w};
            float wv[8] = {w0.x, w0.y, w0.z, w0.w, w1.x, w1.y, w1.z, w1.w};
#pragma unroll
            for (int i = 0; i < 4; i++)
#pragma unroll
                for (int j = 0; j < 8; j++) acc[i][j] += av[i] * wv[j];
        }
        finalScale = s_skip;
    } else {
        finalScale = s_agg;
    }

#pragma unroll
    for (int i = 0; i < 4; i++) {
        int row = row0 + ry * 4 + i;
        if (row < M) {
            int nnode = row / D;
            int ii = row - nnode * D;
            float* op = out + (size_t)nnode * 1024 + outBase + ii;
#pragma unroll
            for (int j = 0; j < 8; j++) {
                op[(size_t)(cx * 8 + j) * D] = acc[i][j] * finalScale;
            }
        }
    }
}

// ---------------- launcher ----------------
extern "C" void kernel_launch(void* const* d_in, const int* in_sizes, int n_in,
                              void* d_out, int out_size)
{
    const float* positions  = (const float*)d_in[0];
    const float* node_feats = (const float*)d_in[1];
    const float* W0  = (const float*)d_in[2];
    const float* W1  = (const float*)d_in[3];
    const float* W2  = (const float*)d_in[4];
    const float* W3  = (const float*)d_in[5];
    const float* Wsc = (const float*)d_in[6];
    const int* senders   = (const int*)d_in[7];
    const int* receivers = (const int*)d_in[8];
    float* out = (float*)d_out;

    int N = in_sizes[0] / 3;
    int E = in_sizes[7];

    float s_skip = (float)(1.0 / sqrt(32.0));          // 1/sqrt(MUL_IN)
    float s_agg  = (float)(1.0 / (8.0 * sqrt(32.0)));  // (1/DENOM)*scale

    // CSR build
    k_zero<<<(N + 255) / 256, 256>>>(N);
    k_hist<<<(E + 255) / 256, 256>>>(receivers, E);
    int nb = (N + 1023) / 1024;
    k_scan1<<<nb, 1024>>>(N);
    k_scan2<<<1, 32>>>(nb);
    k_scan3<<<nb, 1024>>>(N);
    k_scatter<<<(E + 255) / 256, 256>>>(receivers, E);

    // edge phase: warp per node
    k_edge<<<(N + 7) / 8, 256>>>(positions, node_feats, senders, N);

    // node phase: 4 GEMMs
    k_gemm<1, true ><<<(N     + 63) / 64, 128>>>(W0, node_feats, Wsc, out, 0,     N,     0,   s_agg, s_skip);
    k_gemm<3, false><<<(3 * N + 63) / 64, 128>>>(W1, nullptr,    nullptr, out, N,     3 * N, 64,  s_agg, s_skip);
    k_gemm<5, false><<<(5 * N + 63) / 64, 128>>>(W2, nullptr,    nullptr, out, 4 * N, 5 * N, 256, s_agg, s_skip);
    k_gemm<7, false><<<(7 * N + 63) / 64, 128>>>(W3, nullptr,    nullptr, out, 9 * N, 7 * N, 576, s_agg, s_skip);
}

// round 8
// speedup vs baseline: 1.2502x; 1.2502x over previous
#include <cuda_runtime.h>
#include <math.h>

#define N_NODES_MAX 50000
#define N_EDGES_MAX 400000

// ---------------- scratch (device globals; no allocation) ----------------
// agg rows: l0: [0, N)  (n) d=1 | l1: [N,4N) (n*3+i) d=3
//           l2: [4N,9N) (n*5+i) d=5 | l3: [9N,16N) (n*7+i) d=7
// each row has 32 floats (m-contiguous)
__device__ float g_agg[(size_t)16 * N_NODES_MAX * 32];
__device__ int   g_deg[N_NODES_MAX];
__device__ int   g_rowstart[N_NODES_MAX + 1];
__device__ int   g_cursor[N_NODES_MAX];
__device__ int   g_perm[N_EDGES_MAX];
__device__ int   g_bsum[64];
__device__ int   g_boff[64];

// ---------------- f32x2 packed-FMA helpers (FFMA2: PTX-only) ----------------
__device__ __forceinline__ unsigned long long pack2(float a) {
    unsigned long long r;
    asm("mov.b64 %0, {%1, %1};" : "=l"(r) : "f"(a));
    return r;
}
__device__ __forceinline__ void ffma2(unsigned long long& d,
                                      unsigned long long a,
                                      unsigned long long b) {
    asm("fma.rn.f32x2 %0, %1, %2, %0;" : "+l"(d) : "l"(a), "l"(b));
}
__device__ __forceinline__ float2 unpack2(unsigned long long v) {
    float2 f;
    asm("mov.b64 {%0, %1}, %2;" : "=f"(f.x), "=f"(f.y) : "l"(v));
    return f;
}

// ---------------- CSR build ----------------
__global__ void k_zero(int n) {
    int i = blockIdx.x * blockDim.x + threadIdx.x;
    if (i < n) { g_deg[i] = 0; g_cursor[i] = 0; }
}

__global__ void k_hist(const int* __restrict__ recv, int e) {
    int i = blockIdx.x * blockDim.x + threadIdx.x;
    if (i < e) atomicAdd(&g_deg[recv[i]], 1);
}

__global__ void k_scan1(int n) {
    __shared__ int sm[1024];
    int i = blockIdx.x * 1024 + threadIdx.x;
    int v = (i < n) ? g_deg[i] : 0;
    sm[threadIdx.x] = v;
    __syncthreads();
    for (int off = 1; off < 1024; off <<= 1) {
        int t = (threadIdx.x >= off) ? sm[threadIdx.x - off] : 0;
        __syncthreads();
        sm[threadIdx.x] += t;
        __syncthreads();
    }
    if (i < n) g_rowstart[i + 1] = sm[threadIdx.x];
    if (threadIdx.x == 1023) g_bsum[blockIdx.x] = sm[1023];
}

// parallel warp-shfl scan over <=64 block sums (was 1-thread serial, 6.3us)
__global__ void k_scan2(int nb) {
    int t = threadIdx.x;           // blockDim = 64
    int lane = t & 31, w = t >> 5;
    int v = (t < nb) ? g_bsum[t] : 0;
    int s = v;
#pragma unroll
    for (int o = 1; o < 32; o <<= 1) {
        int u = __shfl_up_sync(0xffffffffu, s, o);
        if (lane >= o) s += u;
    }
    __shared__ int warpTot;
    if (w == 0 && lane == 31) warpTot = s;
    __syncthreads();
    if (w == 1) s += warpTot;
    if (t < nb) g_boff[t] = s - v;   // exclusive
    if (t == 0) g_rowstart[0] = 0;
}

__global__ void k_scan3(int n) {
    int i = blockIdx.x * 1024 + threadIdx.x;
    if (i < n) g_rowstart[i + 1] += g_boff[blockIdx.x];
}

__global__ void k_scatter(const int* __restrict__ recv, int e) {
    int i = blockIdx.x * blockDim.x + threadIdx.x;
    if (i < e) {
        int r = recv[i];
        int p = atomicAdd(&g_cursor[r], 1);
        g_perm[g_rowstart[r] + p] = i;
    }
}

// ---------------- edge gather + SH outer-product, warp per node ----------------
__global__ void __launch_bounds__(256) k_edge(
    const float* __restrict__ pos,
    const float* __restrict__ nf,
    const int* __restrict__ send,
    int n)
{
    const float S3  = 1.7320508075688772f;
    const float S5  = 2.2360679774997896f;
    const float S7  = 2.6457513110645906f;
    const float S15 = 3.872983346207417f;
    const float S42 = 6.480740698407860f;
    const float S70 = 8.366600265340756f;
    const float S105 = 10.246950765959598f;

    int warp = (blockIdx.x * blockDim.x + threadIdx.x) >> 5;
    int lane = threadIdx.x & 31;
    if (warp >= n) return;
    int nd = warp;

    float prx = pos[3 * nd + 0];
    float pry = pos[3 * nd + 1];
    float prz = pos[3 * nd + 2];

    float acc[16];
#pragma unroll
    for (int i = 0; i < 16; i++) acc[i] = 0.0f;

    int k0 = g_rowstart[nd];
    int k1 = g_rowstart[nd + 1];
    for (int k = k0; k < k1; k++) {
        int e  = g_perm[k];
        int sn = send[e];
        float sf = nf[(size_t)sn * 32 + lane];
        float dx = prx - pos[3 * sn + 0];
        float dy = pry - pos[3 * sn + 1];
        float dz = prz - pos[3 * sn + 2];
        float rr = sqrtf(dx * dx + dy * dy + dz * dz);
        float inv = 1.0f / fmaxf(rr, 1e-12f);
        float x = dx * inv, y = dy * inv, z = dz * inv;
        float x2 = x * x, y2 = y * y, z2 = z * z;

        acc[0] += sf;
        acc[1] += sf * (S3 * x);
        acc[2] += sf * (S3 * y);
        acc[3] += sf * (S3 * z);
        acc[4] += sf * (S15 * x * y);
        acc[5] += sf * (S15 * y * z);
        acc[6] += sf * (0.5f * S5 * (3.0f * z2 - 1.0f));
        acc[7] += sf * (S15 * x * z);
        acc[8] += sf * (0.5f * S15 * (x2 - y2));
        acc[9]  += sf * (0.25f * S70 * y * (3.0f * x2 - y2));
        acc[10] += sf * (S105 * x * y * z);
        acc[11] += sf * (0.25f * S42 * y * (5.0f * z2 - 1.0f));
        acc[12] += sf * (0.5f * S7 * z * (5.0f * z2 - 3.0f));
        acc[13] += sf * (0.25f * S42 * x * (5.0f * z2 - 1.0f));
        acc[14] += sf * (0.5f * S105 * z * (x2 - y2));
        acc[15] += sf * (0.25f * S70 * x * (x2 - 3.0f * y2));
    }

    g_agg[(size_t)(nd) * 32 + lane] = acc[0];
#pragma unroll
    for (int j = 0; j < 3; j++)
        g_agg[(size_t)(n + nd * 3 + j) * 32 + lane] = acc[1 + j];
#pragma unroll
    for (int j = 0; j < 5; j++)
        g_agg[(size_t)(4 * n + nd * 5 + j) * 32 + lane] = acc[4 + j];
#pragma unroll
    for (int j = 0; j < 7; j++)
        g_agg[(size_t)(9 * n + nd * 7 + j) * 32 + lane] = acc[9 + j];
}

// ---------------- node GEMM: (M x 32) @ (32 x 64) ----------------
// block = 128 threads, tile 64 rows x 64 cols; each thread 4x8 outputs.
// f32x2 packed FMA inner loop; smem-staged coalesced epilogue.
// output element (row = n*D+i, col = t) -> out[n*1024 + outBase + t*D + i]
template <int D, bool SKIP>
__global__ void __launch_bounds__(128) k_gemm(
    const float* __restrict__ W,
    const float* __restrict__ A2,   // node_feats (SKIP only)
    const float* __restrict__ W2,   // Wsc (SKIP only)
    float* __restrict__ out,
    int rowBase, int M, int outBase,
    float s_agg, float s_skip)
{
    __shared__ float smem[6144];                     // 24 KB, aliased
    float (*As)[64]  = (float(*)[64])smem;           // [32][64]
    float (*Ws0)[64] = (float(*)[64])(smem + 2048);  // [32][64]
    float (*Ws1)[64] = (float(*)[64])(smem + 4096);  // [32][64] (SKIP)
    float (*Ot)[65]  = (float(*)[65])smem;           // [64][65] (epilogue, reuse)

    int tid  = threadIdx.x;
    int row0 = blockIdx.x * 64;
    int cx = tid & 7;    // cols cx*8 .. cx*8+7
    int ry = tid >> 3;   // rows ry*4 .. ry*4+3

    // load weights (row-major [m][t] == [k][col])
    for (int idx = tid; idx < 512; idx += 128) {
        ((float4*)&Ws0[0][0])[idx] = ((const float4*)W)[idx];
        if (SKIP) ((float4*)&Ws1[0][0])[idx] = ((const float4*)W2)[idx];
    }

    // load A tile transposed: As[k][r] = agg[(rowBase+row0+r)*32 + k]
    const float* Ag = g_agg + (size_t)rowBase * 32;
    for (int idx = tid; idx < 512; idx += 128) {
        int r = idx >> 3;
        int k4 = (idx & 7) * 4;
        float4 v = make_float4(0.f, 0.f, 0.f, 0.f);
        int row = row0 + r;
        if (row < M) v = *(const float4*)(Ag + (size_t)row * 32 + k4);
        As[k4 + 0][r] = v.x; As[k4 + 1][r] = v.y;
        As[k4 + 2][r] = v.z; As[k4 + 3][r] = v.w;
    }
    __syncthreads();

    unsigned long long accA[4][4];
#pragma unroll
    for (int i = 0; i < 4; i++)
#pragma unroll
        for (int j = 0; j < 4; j++) accA[i][j] = 0ULL;

#pragma unroll
    for (int k = 0; k < 32; k++) {
        float4 a = *(const float4*)&As[k][ry * 4];
        const unsigned long long* wp =
            (const unsigned long long*)&Ws0[k][cx * 8];
        unsigned long long w0 = wp[0], w1 = wp[1], w2 = wp[2], w3 = wp[3];
        unsigned long long a0 = pack2(a.x), a1 = pack2(a.y),
                           a2 = pack2(a.z), a3 = pack2(a.w);
        ffma2(accA[0][0], a0, w0); ffma2(accA[0][1], a0, w1);
        ffma2(accA[0][2], a0, w2); ffma2(accA[0][3], a0, w3);
        ffma2(accA[1][0], a1, w0); ffma2(accA[1][1], a1, w1);
        ffma2(accA[1][2], a1, w2); ffma2(accA[1][3], a1, w3);
        ffma2(accA[2][0], a2, w0); ffma2(accA[2][1], a2, w1);
        ffma2(accA[2][2], a2, w2); ffma2(accA[2][3], a2, w3);
        ffma2(accA[3][0], a3, w0); ffma2(accA[3][1], a3, w1);
        ffma2(accA[3][2], a3, w2); ffma2(accA[3][3], a3, w3);
    }

    unsigned long long accB[4][4];
    if (SKIP) {
#pragma unroll
        for (int i = 0; i < 4; i++)
#pragma unroll
            for (int j = 0; j < 4; j++) accB[i][j] = 0ULL;

        __syncthreads();
        for (int idx = tid; idx < 512; idx += 128) {
            int r = idx >> 3;
            int k4 = (idx & 7) * 4;
            float4 v = make_float4(0.f, 0.f, 0.f, 0.f);
            int row = row0 + r;
            if (row < M) v = *(const float4*)(A2 + (size_t)row * 32 + k4);
            As[k4 + 0][r] = v.x; As[k4 + 1][r] = v.y;
            As[k4 + 2][r] = v.z; As[k4 + 3][r] = v.w;
        }
        __syncthreads();

#pragma unroll
        for (int k = 0; k < 32; k++) {
            float4 a = *(const float4*)&As[k][ry * 4];
            const unsigned long long* wp =
                (const unsigned long long*)&Ws1[k][cx * 8];
            unsigned long long w0 = wp[0], w1 = wp[1], w2 = wp[2], w3 = wp[3];
            unsigned long long a0 = pack2(a.x), a1 = pack2(a.y),
                               a2 = pack2(a.z), a3 = pack2(a.w);
            ffma2(accB[0][0], a0, w0); ffma2(accB[0][1], a0, w1);
            ffma2(accB[0][2], a0, w2); ffma2(accB[0][3], a0, w3);
            ffma2(accB[1][0], a1, w0); ffma2(accB[1][1], a1, w1);
            ffma2(accB[1][2], a1, w2); ffma2(accB[1][3], a1, w3);
            ffma2(accB[2][0], a2, w0); ffma2(accB[2][1], a2, w1);
            ffma2(accB[2][2], a2, w2); ffma2(accB[2][3], a2, w3);
            ffma2(accB[3][0], a3, w0); ffma2(accB[3][1], a3, w1);
            ffma2(accB[3][2], a3, w2); ffma2(accB[3][3], a3, w3);
        }
    }

    // unpack + scale: out0 = accA*s_agg (+ accB*s_skip when SKIP)
    float fin[4][8];
#pragma unroll
    for (int i = 0; i < 4; i++) {
#pragma unroll
        for (int j = 0; j < 4; j++) {
            float2 p = unpack2(accA[i][j]);
            float vx = p.x * s_agg;
            float vy = p.y * s_agg;
            if (SKIP) {
                float2 q = unpack2(accB[i][j]);
                vx += q.x * s_skip;
                vy += q.y * s_skip;
            }
            fin[i][2 * j + 0] = vx;
            fin[i][2 * j + 1] = vy;
        }
    }

    // stage tile in smem, then write out fully coalesced by output address
    __syncthreads();   // everyone done reading As/Ws before aliasing as Ot
#pragma unroll
    for (int i = 0; i < 4; i++)
#pragma unroll
        for (int j = 0; j < 8; j++)
            Ot[ry * 4 + i][cx * 8 + j] = fin[i][j];
    __syncthreads();

    int rEnd   = min(row0 + 64, M);
    int nFirst = row0 / D;
    int nLast  = (rEnd - 1) / D;
    int nNodes = nLast - nFirst + 1;
    int tot    = nNodes * 64 * D;
    for (int m = tid; m < tot; m += 128) {
        int nn = m / (64 * D);
        int q  = m - nn * (64 * D);        // q = t*D + i, linear out offset
        int t  = q / D;
        int i  = q - t * D;
        int node = nFirst + nn;
        int row  = node * D + i;
        if (row >= row0 && row < rEnd)
            out[(size_t)node * 1024 + outBase + q] = Ot[row - row0][t];
    }
}

// ---------------- launcher ----------------
extern "C" void kernel_launch(void* const* d_in, const int* in_sizes, int n_in,
                              void* d_out, int out_size)
{
    const float* positions  = (const float*)d_in[0];
    const float* node_feats = (const float*)d_in[1];
    const float* W0  = (const float*)d_in[2];
    const float* W1  = (const float*)d_in[3];
    const float* W2  = (const float*)d_in[4];
    const float* W3  = (const float*)d_in[5];
    const float* Wsc = (const float*)d_in[6];
    const int* senders   = (const int*)d_in[7];
    const int* receivers = (const int*)d_in[8];
    float* out = (float*)d_out;

    int N = in_sizes[0] / 3;
    int E = in_sizes[7];

    float s_skip = (float)(1.0 / sqrt(32.0));          // 1/sqrt(MUL_IN)
    float s_agg  = (float)(1.0 / (8.0 * sqrt(32.0)));  // (1/DENOM)*scale

    // CSR build
    k_zero<<<(N + 255) / 256, 256>>>(N);
    k_hist<<<(E + 255) / 256, 256>>>(receivers, E);
    int nb = (N + 1023) / 1024;
    k_scan1<<<nb, 1024>>>(N);
    k_scan2<<<1, 64>>>(nb);
    k_scan3<<<nb, 1024>>>(N);
    k_scatter<<<(E + 255) / 256, 256>>>(receivers, E);

    // edge phase: warp per node
    k_edge<<<(N + 7) / 8, 256>>>(positions, node_feats, senders, N);

    // node phase: 4 GEMMs
    k_gemm<1, true ><<<(N     + 63) / 64, 128>>>(W0, node_feats, Wsc, out, 0,     N,     0,   s_agg, s_skip);
    k_gemm<3, false><<<(3 * N + 63) / 64, 128>>>(W1, nullptr,    nullptr, out, N,     3 * N, 64,  s_agg, s_skip);
    k_gemm<5, false><<<(5 * N + 63) / 64, 128>>>(W2, nullptr,    nullptr, out, 4 * N, 5 * N, 256, s_agg, s_skip);
    k_gemm<7, false><<<(7 * N + 63) / 64, 128>>>(W3, nullptr,    nullptr, out, 9 * N, 7 * N, 576, s_agg, s_skip);
}